// round 4
// baseline (speedup 1.0000x reference)
#include <cuda_runtime.h>
#include <math.h>

// Problem constants (fixed by the reference)
#define NN 50000
#define EE 800000
#define IN_C 128
#define HIDC 64
#define HEADS 4
#define TC1 (HEADS * HIDC)   // 256
#define NUM_CLASSES 10
#define NUM_GRAPHS 64
#define EPS 1e-5f
#define NEG_SLOPE 0.2f

#define SCAN_B 512
#define SCAN_NB ((NN + SCAN_B - 1) / SCAN_B)   // 98

// ---------------- device scratch (static globals: no allocation) -------------
__device__ float g_h[(size_t)NN * 256];     // GEMM output / h of current layer
__device__ float g_o[(size_t)NN * 256];     // aggregation output / next input
__device__ float g_as[(size_t)NN * HEADS];
__device__ float g_ad[(size_t)NN * HEADS];
__device__ int   g_rowptr[NN + 1];
__device__ int   g_rowcur[NN];
__device__ int   g_counts[NN];
__device__ int   g_bsums[SCAN_NB + 8];
__device__ int   g_srcs[EE];
__device__ float g_sum[256];
__device__ float g_sumsq[256];
__device__ float g_Weff[256 * 256];
__device__ float g_cvec[256];
__device__ float g_gsum[NUM_GRAPHS * HIDC];
__device__ int   g_gcnt[NUM_GRAPHS];

// ---------------- small init kernels -----------------------------------------
__global__ void zero_counts_kernel() {
    int i = blockIdx.x * blockDim.x + threadIdx.x;
    if (i < NN) g_counts[i] = 0;
}
__global__ void zero_stats_kernel() {
    int i = threadIdx.x;
    g_sum[i] = 0.f; g_sumsq[i] = 0.f;
}
__global__ void zero_pool_kernel() {
    int i = blockIdx.x * blockDim.x + threadIdx.x;
    if (i < NUM_GRAPHS * HIDC) g_gsum[i] = 0.f;
    if (i < NUM_GRAPHS) g_gcnt[i] = 0;
}

// ---------------- CSR build ---------------------------------------------------
__global__ void count_kernel(const int* __restrict__ dst) {
    int i = blockIdx.x * blockDim.x + threadIdx.x;
    for (; i < EE; i += gridDim.x * blockDim.x)
        atomicAdd(&g_counts[dst[i]], 1);
}

__global__ void scan_block_kernel() {
    __shared__ int sm[SCAN_B];
    int tid = threadIdx.x;
    int i = blockIdx.x * SCAN_B + tid;
    int v = (i < NN) ? g_counts[i] : 0;
    sm[tid] = v;
    __syncthreads();
    for (int off = 1; off < SCAN_B; off <<= 1) {
        int t = (tid >= off) ? sm[tid - off] : 0;
        __syncthreads();
        sm[tid] += t;
        __syncthreads();
    }
    if (i < NN) g_rowptr[i + 1] = sm[tid];
    if (tid == SCAN_B - 1) g_bsums[blockIdx.x] = sm[tid];
}

__global__ void scan_sums_kernel() {
    if (threadIdx.x == 0) {
        int a = 0;
        for (int i = 0; i < SCAN_NB; i++) { int t = g_bsums[i]; g_bsums[i] = a; a += t; }
        g_rowptr[0] = 0;
    }
}

__global__ void add_offsets_kernel() {
    int i = blockIdx.x * SCAN_B + threadIdx.x;
    if (i < NN) {
        int r = g_rowptr[i + 1] + g_bsums[blockIdx.x];
        g_rowptr[i + 1] = r;
        g_rowcur[i] = 0;  // init later via init_rowcur
    }
}

__global__ void init_rowcur_kernel() {
    int i = blockIdx.x * blockDim.x + threadIdx.x;
    if (i < NN) g_rowcur[i] = g_rowptr[i];
}

__global__ void scatter_kernel(const int* __restrict__ src, const int* __restrict__ dst) {
    int i = blockIdx.x * blockDim.x + threadIdx.x;
    for (; i < EE; i += gridDim.x * blockDim.x) {
        int d = dst[i];
        int pos = atomicAdd(&g_rowcur[d], 1);
        g_srcs[pos] = src[i];
    }
}

// ---------------- tiled fp32 GEMM: C[M,N] = A[M,K] @ B[K,N] (+bias) -----------
#define GBM 128
#define GBN 64
#define GBK 16
__global__ void __launch_bounds__(256)
gemm_kernel(const float* __restrict__ A, const float* __restrict__ B,
            const float* __restrict__ bias, float* __restrict__ C,
            int M, int N, int K)
{
    __shared__ float As[GBK][GBM + 4];
    __shared__ __align__(16) float Bs[GBK][GBN];
    int tid = threadIdx.x;
    int tx = tid & 15;   // col group (4 cols)
    int ty = tid >> 4;   // row group (8 rows)
    int row0 = blockIdx.x * GBM;
    int col0 = blockIdx.y * GBN;

    float acc[8][4];
#pragma unroll
    for (int i = 0; i < 8; i++)
#pragma unroll
        for (int j = 0; j < 4; j++) acc[i][j] = 0.f;

    for (int k0 = 0; k0 < K; k0 += GBK) {
        // A tile: 128x16, transposed into As[k][m]; 2 float4 per thread
#pragma unroll
        for (int it = 0; it < 2; it++) {
            int idx = tid + it * 256;
            int ar = idx >> 2;
            int ac = (idx & 3) * 4;
            int gr = row0 + ar;
            float4 v = make_float4(0.f, 0.f, 0.f, 0.f);
            if (gr < M) v = *reinterpret_cast<const float4*>(A + (size_t)gr * K + k0 + ac);
            As[ac + 0][ar] = v.x; As[ac + 1][ar] = v.y;
            As[ac + 2][ar] = v.z; As[ac + 3][ar] = v.w;
        }
        // B tile: 16x64; 1 float4 per thread (K%16==0, N%64==0 guaranteed)
        {
            int br = tid >> 4;
            int bc = (tid & 15) * 4;
            float4 v = *reinterpret_cast<const float4*>(B + (size_t)(k0 + br) * N + col0 + bc);
            *reinterpret_cast<float4*>(&Bs[br][bc]) = v;
        }
        __syncthreads();
#pragma unroll
        for (int kk = 0; kk < GBK; kk++) {
            float af[8], bf[4];
#pragma unroll
            for (int i = 0; i < 8; i++) af[i] = As[kk][ty * 8 + i];
#pragma unroll
            for (int j = 0; j < 4; j++) bf[j] = Bs[kk][tx * 4 + j];
#pragma unroll
            for (int i = 0; i < 8; i++)
#pragma unroll
                for (int j = 0; j < 4; j++) acc[i][j] += af[i] * bf[j];
        }
        __syncthreads();
    }
#pragma unroll
    for (int i = 0; i < 8; i++) {
        int gr = row0 + ty * 8 + i;
        if (gr < M) {
#pragma unroll
            for (int j = 0; j < 4; j++) {
                int gc = col0 + tx * 4 + j;
                float v = acc[i][j];
                if (bias) v += bias[gc];
                C[(size_t)gr * N + gc] = v;
            }
        }
    }
}

// ---------------- per-node attention logits (warp per node) -------------------
template <int H, int C>
__global__ void attn_kernel(const float* __restrict__ hbuf,
                            const float* __restrict__ a_src,
                            const float* __restrict__ a_dst)
{
    const int TC = H * C;
    const int CPL = TC / 32;
    const int GRP = 32 / H;
    int wid = (blockIdx.x * blockDim.x + threadIdx.x) >> 5;
    int lane = threadIdx.x & 31;
    if (wid >= NN) return;
    int cb = lane * CPL;
    int hd = cb / C;
    int c0 = cb % C;
    const float* hp = hbuf + (size_t)wid * TC + cb;
    float sa = 0.f, sd = 0.f;
#pragma unroll
    for (int i = 0; i < CPL; i++) {
        float hv = hp[i];
        sa += hv * a_src[hd * C + c0 + i];
        sd += hv * a_dst[hd * C + c0 + i];
    }
#pragma unroll
    for (int off = GRP / 2; off > 0; off >>= 1) {
        sa += __shfl_xor_sync(0xffffffffu, sa, off);
        sd += __shfl_xor_sync(0xffffffffu, sd, off);
    }
    if ((lane & (GRP - 1)) == 0) {
        g_as[wid * H + hd] = sa;
        g_ad[wid * H + hd] = sd;
    }
}

// ---------------- aggregation: warp per dst node, CSR two-pass softmax --------
template <int H, int C>
__global__ void __launch_bounds__(256)
agg_kernel(const float* __restrict__ hbuf, const float* __restrict__ bias,
           float* __restrict__ outbuf)
{
    const int TC = H * C;
    const int CPL = TC / 32;     // 8 (H=4) or 2 (H=1)
    int wid = (blockIdx.x * blockDim.x + threadIdx.x) >> 5;
    int lane = threadIdx.x & 31;
    if (wid >= NN) return;
    int cb = lane * CPL;
    int hd = cb / C;
    int r0 = g_rowptr[wid];
    int r1 = g_rowptr[wid + 1];
    float adv = g_ad[wid * H + hd];

    // pass 1: per-head max
    float m = -1e30f;
    for (int e = r0; e < r1; e++) {
        int s = g_srcs[e];
        float ev = g_as[s * H + hd] + adv;
        ev = (ev > 0.f) ? ev : NEG_SLOPE * ev;
        m = fmaxf(m, ev);
    }

    // pass 2: exp-sum + weighted accumulation
    float den = 0.f;
    float acc[CPL];
#pragma unroll
    for (int i = 0; i < CPL; i++) acc[i] = 0.f;
    for (int e = r0; e < r1; e++) {
        int s = g_srcs[e];
        float ev = g_as[s * H + hd] + adv;
        ev = (ev > 0.f) ? ev : NEG_SLOPE * ev;
        float p = expf(ev - m);
        den += p;
        const float2* hp = reinterpret_cast<const float2*>(hbuf + (size_t)s * TC + cb);
#pragma unroll
        for (int q = 0; q < CPL / 2; q++) {
            float2 v = hp[q];
            acc[q * 2 + 0] += p * v.x;
            acc[q * 2 + 1] += p * v.y;
        }
    }

    float inv = (r1 > r0) ? (1.f / den) : 0.f;
#pragma unroll
    for (int i = 0; i < CPL; i++) {
        float o = acc[i] * inv + bias[cb + i];
        outbuf[(size_t)wid * TC + cb + i] = fmaxf(o, 0.f);
    }
}

// ---------------- per-channel sum / sumsq (for BN fold) -----------------------
template <int C>
__global__ void stats_kernel(const float* __restrict__ buf)
{
    const int RPB = 256 / C;
    int ch = threadIdx.x % C;
    int r = blockIdx.x * RPB + threadIdx.x / C;
    int stride = gridDim.x * RPB;
    float s = 0.f, s2 = 0.f;
    for (; r < NN; r += stride) {
        float v = buf[(size_t)r * C + ch];
        s += v;
        s2 += v * v;
    }
    atomicAdd(&g_sum[ch], s);
    atomicAdd(&g_sumsq[ch], s2);
}

// ---------------- fold BN (s,t) into next weight matrix -----------------------
// Weff[k][j] = s[k]*W[k][j];  cvec[j] = sum_k t[k]*W[k][j]
__global__ void fold_kernel(const float* __restrict__ W,
                            const float* __restrict__ gamma,
                            const float* __restrict__ beta,
                            int cout)
{
    __shared__ float red[256];
    int j = blockIdx.x;
    int k = threadIdx.x;   // cin = 256 always
    const float invN = 1.f / (float)NN;
    float mean = g_sum[k] * invN;
    float var  = g_sumsq[k] * invN - mean * mean;
    float s = gamma[k] * rsqrtf(var + EPS);
    float t = beta[k] - mean * s;
    float w = W[k * cout + j];
    g_Weff[k * cout + j] = s * w;
    red[k] = t * w;
    __syncthreads();
    for (int off = 128; off > 0; off >>= 1) {
        if (k < off) red[k] += red[k + off];
        __syncthreads();
    }
    if (k == 0) g_cvec[j] = red[0];
}

// ---------------- pooling + classifier ----------------------------------------
__global__ void pool_kernel(const int* __restrict__ batch)
{
    int i = blockIdx.x * blockDim.x + threadIdx.x;
    int total = NN * HIDC;
    for (; i < total; i += gridDim.x * blockDim.x) {
        int node = i >> 6;
        int ch = i & 63;
        int gidx = batch[node];
        atomicAdd(&g_gsum[gidx * HIDC + ch], g_o[(size_t)node * HIDC + ch]);
        if (ch == 0) atomicAdd(&g_gcnt[gidx], 1);
    }
}

__global__ void final_kernel(const float* __restrict__ g3, const float* __restrict__ be3,
                             const float* __restrict__ fcW, const float* __restrict__ fcb,
                             float* __restrict__ out)
{
    __shared__ float z[HIDC];
    int g = blockIdx.x;
    int ch = threadIdx.x;
    const float invN = 1.f / (float)NN;
    float cnt = fmaxf((float)g_gcnt[g], 1.f);
    float pooled = g_gsum[g * HIDC + ch] / cnt;
    float mean = g_sum[ch] * invN;
    float var  = g_sumsq[ch] * invN - mean * mean;
    float s = g3[ch] * rsqrtf(var + EPS);
    float t = be3[ch] - mean * s;
    z[ch] = pooled * s + t;
    __syncthreads();
    if (ch < NUM_CLASSES) {
        float a = fcb[ch];
        for (int c = 0; c < HIDC; c++) a += z[c] * fcW[c * NUM_CLASSES + ch];
        out[g * NUM_CLASSES + ch] = a;
    }
}

// ---------------- driver -------------------------------------------------------
extern "C" void kernel_launch(void* const* d_in, const int* in_sizes, int n_in,
                              void* d_out, int out_size)
{
    const float* x      = (const float*)d_in[0];
    const int*   ei     = (const int*)d_in[1];
    const int*   batch  = (const int*)d_in[2];
    const float* W1     = (const float*)d_in[3];
    const float* as1    = (const float*)d_in[4];
    const float* ad1    = (const float*)d_in[5];
    const float* b1     = (const float*)d_in[6];
    const float* gm1    = (const float*)d_in[7];
    const float* be1    = (const float*)d_in[8];
    const float* W2     = (const float*)d_in[9];
    const float* as2    = (const float*)d_in[10];
    const float* ad2    = (const float*)d_in[11];
    const float* b2     = (const float*)d_in[12];
    const float* gm2    = (const float*)d_in[13];
    const float* be2    = (const float*)d_in[14];
    const float* W3     = (const float*)d_in[15];
    const float* as3    = (const float*)d_in[16];
    const float* ad3    = (const float*)d_in[17];
    const float* b3     = (const float*)d_in[18];
    const float* gm3    = (const float*)d_in[19];
    const float* be3    = (const float*)d_in[20];
    const float* fcW    = (const float*)d_in[21];
    const float* fcb    = (const float*)d_in[22];
    float* out = (float*)d_out;

    const int* e_src = ei;
    const int* e_dst = ei + EE;

    // device pointers to scratch
    float *p_h, *p_o, *p_Weff, *p_cvec;
    cudaGetSymbolAddress((void**)&p_h,    g_h);
    cudaGetSymbolAddress((void**)&p_o,    g_o);
    cudaGetSymbolAddress((void**)&p_Weff, g_Weff);
    cudaGetSymbolAddress((void**)&p_cvec, g_cvec);

    const int warpBlocks = (NN * 32 + 255) / 256;  // warp-per-node kernels

    // ---- CSR build (every call; no caching) ----
    zero_counts_kernel<<<(NN + 255) / 256, 256>>>();
    count_kernel<<<1024, 256>>>(e_dst);
    scan_block_kernel<<<SCAN_NB, SCAN_B>>>();
    scan_sums_kernel<<<1, 32>>>();
    add_offsets_kernel<<<SCAN_NB, SCAN_B>>>();
    init_rowcur_kernel<<<(NN + 255) / 256, 256>>>();
    scatter_kernel<<<1024, 256>>>(e_src, e_dst);

    // ---- layer 1: h = x @ W1 ; attn ; aggregate ; stats ; fold into W2 ----
    {
        dim3 grid((NN + GBM - 1) / GBM, TC1 / GBN);
        gemm_kernel<<<grid, 256>>>(x, W1, nullptr, p_h, NN, TC1, IN_C);
    }
    attn_kernel<HEADS, HIDC><<<warpBlocks, 256>>>(p_h, as1, ad1);
    agg_kernel<HEADS, HIDC><<<warpBlocks, 256>>>(p_h, b1, p_o);
    zero_stats_kernel<<<1, 256>>>();
    stats_kernel<256><<<512, 256>>>(p_o);
    fold_kernel<<<TC1, 256>>>(W2, gm1, be1, TC1);

    // ---- layer 2 ----
    {
        dim3 grid((NN + GBM - 1) / GBM, TC1 / GBN);
        gemm_kernel<<<grid, 256>>>(p_o, p_Weff, p_cvec, p_h, NN, TC1, TC1);
    }
    attn_kernel<HEADS, HIDC><<<warpBlocks, 256>>>(p_h, as2, ad2);
    agg_kernel<HEADS, HIDC><<<warpBlocks, 256>>>(p_h, b2, p_o);
    zero_stats_kernel<<<1, 256>>>();
    stats_kernel<256><<<512, 256>>>(p_o);
    fold_kernel<<<HIDC, 256>>>(W3, gm2, be2, HIDC);

    // ---- layer 3 (H=1, C=64) ----
    {
        dim3 grid((NN + GBM - 1) / GBM, HIDC / GBN);
        gemm_kernel<<<grid, 256>>>(p_o, p_Weff, p_cvec, p_h, NN, HIDC, TC1);
    }
    attn_kernel<1, HIDC><<<warpBlocks, 256>>>(p_h, as3, ad3);
    agg_kernel<1, HIDC><<<warpBlocks, 256>>>(p_h, b3, p_o);
    zero_stats_kernel<<<1, 256>>>();
    stats_kernel<64><<<512, 256>>>(p_o);

    // ---- pool + BN3-folded classifier ----
    zero_pool_kernel<<<16, 256>>>();
    pool_kernel<<<2048, 256>>>(batch);
    final_kernel<<<NUM_GRAPHS, HIDC>>>(gm3, be3, fcW, fcb, out);
}

// round 5
// speedup vs baseline: 1.9484x; 1.9484x over previous
#include <cuda_runtime.h>
#include <math.h>

// Problem constants (fixed by the reference)
#define NN 50000
#define EE 800000
#define IN_C 128
#define HIDC 64
#define HEADS 4
#define TC1 (HEADS * HIDC)   // 256
#define NUM_CLASSES 10
#define NUM_GRAPHS 64
#define EPS 1e-5f
#define NEG_SLOPE 0.2f

#define SCAN_B 512
#define SCAN_NB ((NN + SCAN_B - 1) / SCAN_B)   // 98

// ---------------- device scratch (static globals: no allocation) -------------
__device__ float g_h[(size_t)NN * 256];     // GEMM output / h of current layer
__device__ float g_o[(size_t)NN * 256];     // aggregation output / next input
__device__ float g_as[(size_t)NN * HEADS];
__device__ float g_ad[(size_t)NN * HEADS];
__device__ int   g_rowptr[NN + 1];
__device__ int   g_rowcur[NN];
__device__ int   g_counts[NN];
__device__ int   g_bsums[SCAN_NB + 8];
__device__ int   g_srcs[EE];
__device__ float g_sum[256];
__device__ float g_sumsq[256];
__device__ float g_Weff[256 * 256];
__device__ float g_cvec[256];
__device__ float g_gsum[NUM_GRAPHS * HIDC];
__device__ int   g_gcnt[NUM_GRAPHS];

// ---------------- small init kernels -----------------------------------------
__global__ void zero_counts_kernel() {
    int i = blockIdx.x * blockDim.x + threadIdx.x;
    if (i < NN) g_counts[i] = 0;
}
__global__ void zero_stats_kernel() {
    int i = threadIdx.x;
    g_sum[i] = 0.f; g_sumsq[i] = 0.f;
}
__global__ void zero_pool_kernel() {
    int i = blockIdx.x * blockDim.x + threadIdx.x;
    if (i < NUM_GRAPHS * HIDC) g_gsum[i] = 0.f;
    if (i < NUM_GRAPHS) g_gcnt[i] = 0;
}

// ---------------- CSR build ---------------------------------------------------
__global__ void count_kernel(const int* __restrict__ dst) {
    int i = blockIdx.x * blockDim.x + threadIdx.x;
    for (; i < EE; i += gridDim.x * blockDim.x)
        atomicAdd(&g_counts[dst[i]], 1);
}

__global__ void scan_block_kernel() {
    __shared__ int sm[SCAN_B];
    int tid = threadIdx.x;
    int i = blockIdx.x * SCAN_B + tid;
    int v = (i < NN) ? g_counts[i] : 0;
    sm[tid] = v;
    __syncthreads();
    for (int off = 1; off < SCAN_B; off <<= 1) {
        int t = (tid >= off) ? sm[tid - off] : 0;
        __syncthreads();
        sm[tid] += t;
        __syncthreads();
    }
    if (i < NN) g_rowptr[i + 1] = sm[tid];
    if (tid == SCAN_B - 1) g_bsums[blockIdx.x] = sm[tid];
}

// parallel exclusive scan over block sums (98 values)
__global__ void scan_sums_kernel() {
    __shared__ int sm[128];
    int t = threadIdx.x;
    int v = (t < SCAN_NB) ? g_bsums[t] : 0;
    sm[t] = v;
    __syncthreads();
    for (int off = 1; off < 128; off <<= 1) {
        int u = (t >= off) ? sm[t - off] : 0;
        __syncthreads();
        sm[t] += u;
        __syncthreads();
    }
    if (t < SCAN_NB) g_bsums[t] = sm[t] - v;  // exclusive prefix
    if (t == 0) g_rowptr[0] = 0;
}

__global__ void add_offsets_kernel() {
    int i = blockIdx.x * SCAN_B + threadIdx.x;
    if (i < NN) {
        int r = g_rowptr[i + 1] + g_bsums[blockIdx.x];
        g_rowptr[i + 1] = r;
        if (i + 1 < NN) g_rowcur[i + 1] = r;   // rowcur init fused here
        if (i == 0) g_rowcur[0] = 0;
    }
}

__global__ void scatter_kernel(const int* __restrict__ src, const int* __restrict__ dst) {
    int i = blockIdx.x * blockDim.x + threadIdx.x;
    for (; i < EE; i += gridDim.x * blockDim.x) {
        int d = dst[i];
        int pos = atomicAdd(&g_rowcur[d], 1);
        g_srcs[pos] = src[i];
    }
}

// ---------------- f32x2 GEMM with fused attention-logit epilogue --------------
// C[M,N] = A[M,K] @ B[K,N] (+bias); also writes g_as/g_ad per (node, head).
// BM=128, BK=16; BN templated (128 or 64). Per-thread TM x 8 output via packed
// fma.rn.f32x2 (FFMA2) -- 2x fp32 FMA throughput vs scalar FFMA on sm_103a.
template<int BN, int H>
__global__ void __launch_bounds__(256, 2)
gemm_attn_kernel(const float* __restrict__ A, const float* __restrict__ B,
                 const float* __restrict__ bias, float* __restrict__ C,
                 const float* __restrict__ a_src, const float* __restrict__ a_dst,
                 int M, int N, int K)
{
    const int BM = 128, BK = 16;
    const int TX = BN / 8;          // col groups of 8
    const int TY = 256 / TX;        // row groups
    const int TM = BM / TY;         // rows per thread (8 or 4)
    const int LB = (BK * BN) / 1024;  // float4 B loads per thread (2 or 1)

    __shared__ float As[BK][BM + 4];
    __shared__ __align__(16) float Bs[BK][BN];

    int tid = threadIdx.x;
    int tx = tid % TX, ty = tid / TX;
    int row0 = blockIdx.x * BM, col0 = blockIdx.y * BN;
    int r0 = ty * TM, c0 = tx * 8;

    unsigned long long acc[TM][4];
#pragma unroll
    for (int i = 0; i < TM; i++)
#pragma unroll
        for (int j = 0; j < 4; j++) acc[i][j] = 0ull;

    float4 pa[2], pb[LB];

    // --- prefetch tile k0=0 into registers ---
#pragma unroll
    for (int it = 0; it < 2; it++) {
        int idx = tid + it * 256;
        int ar = idx >> 2, ac = (idx & 3) * 4;
        int gr = row0 + ar;
        pa[it] = make_float4(0.f, 0.f, 0.f, 0.f);
        if (gr < M) pa[it] = *reinterpret_cast<const float4*>(A + (size_t)gr * K + ac);
    }
#pragma unroll
    for (int it = 0; it < LB; it++) {
        int idx = tid + it * 256;
        int br = idx / (BN / 4), bc = (idx % (BN / 4)) * 4;
        pb[it] = *reinterpret_cast<const float4*>(B + (size_t)br * N + col0 + bc);
    }

    for (int k0 = 0; k0 < K; k0 += BK) {
        // store prefetched tile to smem
#pragma unroll
        for (int it = 0; it < 2; it++) {
            int idx = tid + it * 256;
            int ar = idx >> 2, ac = (idx & 3) * 4;
            As[ac + 0][ar] = pa[it].x; As[ac + 1][ar] = pa[it].y;
            As[ac + 2][ar] = pa[it].z; As[ac + 3][ar] = pa[it].w;
        }
#pragma unroll
        for (int it = 0; it < LB; it++) {
            int idx = tid + it * 256;
            int br = idx / (BN / 4), bc = (idx % (BN / 4)) * 4;
            *reinterpret_cast<float4*>(&Bs[br][bc]) = pb[it];
        }
        __syncthreads();

        // prefetch next tile (overlaps with compute below)
        bool has_next = (k0 + BK) < K;
        if (has_next) {
            int kn = k0 + BK;
#pragma unroll
            for (int it = 0; it < 2; it++) {
                int idx = tid + it * 256;
                int ar = idx >> 2, ac = (idx & 3) * 4;
                int gr = row0 + ar;
                pa[it] = make_float4(0.f, 0.f, 0.f, 0.f);
                if (gr < M) pa[it] = *reinterpret_cast<const float4*>(A + (size_t)gr * K + kn + ac);
            }
#pragma unroll
            for (int it = 0; it < LB; it++) {
                int idx = tid + it * 256;
                int br = idx / (BN / 4), bc = (idx % (BN / 4)) * 4;
                pb[it] = *reinterpret_cast<const float4*>(B + (size_t)(kn + br) * N + col0 + bc);
            }
        }

        // compute (FFMA2 inner loop)
#pragma unroll
        for (int kk = 0; kk < BK; kk++) {
            unsigned long long bp[4];
            const unsigned long long* brow =
                reinterpret_cast<const unsigned long long*>(&Bs[kk][c0]);
#pragma unroll
            for (int j = 0; j < 4; j++) bp[j] = brow[j];
#pragma unroll
            for (int i = 0; i < TM; i++) {
                float a = As[kk][r0 + i];
                unsigned long long ap;
                asm("mov.b64 %0, {%1, %1};" : "=l"(ap) : "f"(a));
#pragma unroll
                for (int j = 0; j < 4; j++)
                    asm("fma.rn.f32x2 %0, %1, %2, %0;"
                        : "+l"(acc[i][j]) : "l"(ap), "l"(bp[j]));
            }
        }
        __syncthreads();
    }

    // --- epilogue: bias, store C, fused attention logits ---
    int hd  = (col0 + c0) >> 6;     // head (C=64 always)
    int cih = (col0 + c0) & 63;     // channel within head
    float bv[8], av[8], dv[8];
#pragma unroll
    for (int j = 0; j < 8; j++) {
        bv[j] = bias ? bias[col0 + c0 + j] : 0.f;
        av[j] = a_src[hd * 64 + cih + j];
        dv[j] = a_dst[hd * 64 + cih + j];
    }

#pragma unroll
    for (int i = 0; i < TM; i++) {
        int gr = row0 + r0 + i;
        float v[8];
#pragma unroll
        for (int j = 0; j < 4; j++) {
            float lo, hi;
            asm("mov.b64 {%0, %1}, %2;" : "=f"(lo), "=f"(hi) : "l"(acc[i][j]));
            v[2 * j]     = lo + bv[2 * j];
            v[2 * j + 1] = hi + bv[2 * j + 1];
        }
        float sa = 0.f, sd = 0.f;
#pragma unroll
        for (int j = 0; j < 8; j++) { sa += v[j] * av[j]; sd += v[j] * dv[j]; }
        // reduce across the 8 lanes covering this head (lane groups of 8)
#pragma unroll
        for (int off = 4; off > 0; off >>= 1) {
            sa += __shfl_xor_sync(0xffffffffu, sa, off);
            sd += __shfl_xor_sync(0xffffffffu, sd, off);
        }
        if (gr < M) {
            float* cp = C + (size_t)gr * N + col0 + c0;
            *reinterpret_cast<float4*>(cp)     = make_float4(v[0], v[1], v[2], v[3]);
            *reinterpret_cast<float4*>(cp + 4) = make_float4(v[4], v[5], v[6], v[7]);
            if ((tx & 7) == 0) {
                g_as[(size_t)gr * H + hd] = sa;
                g_ad[(size_t)gr * H + hd] = sd;
            }
        }
    }
}

// ---------------- aggregation: warp per dst node, single-pass softmax ---------
template <int H, int C>
__global__ void __launch_bounds__(256)
agg_kernel(const float* __restrict__ hbuf, const float* __restrict__ bias,
           float* __restrict__ outbuf)
{
    const int TC = H * C;
    const int CPL = TC / 32;     // 8 (H=4) or 2 (H=1)
    int wid = (blockIdx.x * blockDim.x + threadIdx.x) >> 5;
    int lane = threadIdx.x & 31;
    if (wid >= NN) return;
    int cb = lane * CPL;
    int hd = cb / C;
    int r0 = g_rowptr[wid];
    int r1 = g_rowptr[wid + 1];
    float adv = g_ad[(size_t)wid * H + hd];

    float den = 0.f;
    float acc[CPL];
#pragma unroll
    for (int i = 0; i < CPL; i++) acc[i] = 0.f;

    for (int e = r0; e < r1; e++) {
        int s = g_srcs[e];
        float ev = g_as[(size_t)s * H + hd] + adv;
        ev = (ev > 0.f) ? ev : NEG_SLOPE * ev;
        float p = __expf(fminf(ev, 60.f));
        den += p;
        const float* hp = hbuf + (size_t)s * TC + cb;
        if (CPL == 2) {
            float2 vv = *reinterpret_cast<const float2*>(hp);
            acc[0] += p * vv.x;
            acc[1] += p * vv.y;
        } else {
#pragma unroll
            for (int q = 0; q < CPL / 4; q++) {
                float4 vv = reinterpret_cast<const float4*>(hp)[q];
                acc[q * 4 + 0] += p * vv.x;
                acc[q * 4 + 1] += p * vv.y;
                acc[q * 4 + 2] += p * vv.z;
                acc[q * 4 + 3] += p * vv.w;
            }
        }
    }

    float inv = (r1 > r0) ? (1.f / den) : 0.f;
#pragma unroll
    for (int i = 0; i < CPL; i++) {
        float o = acc[i] * inv + bias[cb + i];
        outbuf[(size_t)wid * TC + cb + i] = fmaxf(o, 0.f);
    }
}

// ---------------- per-channel sum / sumsq (for BN fold) -----------------------
template <int C>
__global__ void stats_kernel(const float* __restrict__ buf)
{
    const int RPB = 256 / C;
    int ch = threadIdx.x % C;
    int r = blockIdx.x * RPB + threadIdx.x / C;
    int stride = gridDim.x * RPB;
    float s = 0.f, s2 = 0.f;
    for (; r < NN; r += stride) {
        float v = buf[(size_t)r * C + ch];
        s += v;
        s2 += v * v;
    }
    atomicAdd(&g_sum[ch], s);
    atomicAdd(&g_sumsq[ch], s2);
}

// ---------------- fold BN (s,t) into next weight matrix -----------------------
__global__ void fold_kernel(const float* __restrict__ W,
                            const float* __restrict__ gamma,
                            const float* __restrict__ beta,
                            int cout)
{
    __shared__ float red[256];
    int j = blockIdx.x;
    int k = threadIdx.x;   // cin = 256 always
    const float invN = 1.f / (float)NN;
    float mean = g_sum[k] * invN;
    float var  = g_sumsq[k] * invN - mean * mean;
    float s = gamma[k] * rsqrtf(var + EPS);
    float t = beta[k] - mean * s;
    float w = W[k * cout + j];
    g_Weff[k * cout + j] = s * w;
    red[k] = t * w;
    __syncthreads();
    for (int off = 128; off > 0; off >>= 1) {
        if (k < off) red[k] += red[k + off];
        __syncthreads();
    }
    if (k == 0) g_cvec[j] = red[0];
}

// ---------------- pooling (exploits sorted batch) + classifier ----------------
#define POOL_NPB 256
__global__ void pool_kernel(const int* __restrict__ batch)
{
    int n0 = blockIdx.x * POOL_NPB;
    int ch = threadIdx.x & 63;
    int sub = threadIdx.x >> 6;    // 0..3
    float accv = 0.f;
    int cur = -1, cnt = 0;
    int nend = n0 + POOL_NPB; if (nend > NN) nend = NN;
    for (int node = n0 + sub; node < nend; node += 4) {
        int g = batch[node];
        if (g != cur) {
            if (cur >= 0) {
                atomicAdd(&g_gsum[cur * HIDC + ch], accv);
                if (ch == 0) atomicAdd(&g_gcnt[cur], cnt);
            }
            cur = g; accv = 0.f; cnt = 0;
        }
        accv += g_o[(size_t)node * HIDC + ch];
        cnt++;
    }
    if (cur >= 0) {
        atomicAdd(&g_gsum[cur * HIDC + ch], accv);
        if (ch == 0) atomicAdd(&g_gcnt[cur], cnt);
    }
}

__global__ void final_kernel(const float* __restrict__ g3, const float* __restrict__ be3,
                             const float* __restrict__ fcW, const float* __restrict__ fcb,
                             float* __restrict__ out)
{
    __shared__ float z[HIDC];
    int g = blockIdx.x;
    int ch = threadIdx.x;
    const float invN = 1.f / (float)NN;
    float cnt = fmaxf((float)g_gcnt[g], 1.f);
    float pooled = g_gsum[g * HIDC + ch] / cnt;
    float mean = g_sum[ch] * invN;
    float var  = g_sumsq[ch] * invN - mean * mean;
    float s = g3[ch] * rsqrtf(var + EPS);
    float t = be3[ch] - mean * s;
    z[ch] = pooled * s + t;
    __syncthreads();
    if (ch < NUM_CLASSES) {
        float a = fcb[ch];
        for (int c = 0; c < HIDC; c++) a += z[c] * fcW[c * NUM_CLASSES + ch];
        out[g * NUM_CLASSES + ch] = a;
    }
}

// ---------------- driver -------------------------------------------------------
extern "C" void kernel_launch(void* const* d_in, const int* in_sizes, int n_in,
                              void* d_out, int out_size)
{
    const float* x      = (const float*)d_in[0];
    const int*   ei     = (const int*)d_in[1];
    const int*   batch  = (const int*)d_in[2];
    const float* W1     = (const float*)d_in[3];
    const float* as1    = (const float*)d_in[4];
    const float* ad1    = (const float*)d_in[5];
    const float* b1     = (const float*)d_in[6];
    const float* gm1    = (const float*)d_in[7];
    const float* be1    = (const float*)d_in[8];
    const float* W2     = (const float*)d_in[9];
    const float* as2    = (const float*)d_in[10];
    const float* ad2    = (const float*)d_in[11];
    const float* b2     = (const float*)d_in[12];
    const float* gm2    = (const float*)d_in[13];
    const float* be2    = (const float*)d_in[14];
    const float* W3     = (const float*)d_in[15];
    const float* as3    = (const float*)d_in[16];
    const float* ad3    = (const float*)d_in[17];
    const float* b3     = (const float*)d_in[18];
    const float* gm3    = (const float*)d_in[19];
    const float* be3    = (const float*)d_in[20];
    const float* fcW    = (const float*)d_in[21];
    const float* fcb    = (const float*)d_in[22];
    float* out = (float*)d_out;

    const int* e_src = ei;
    const int* e_dst = ei + EE;

    float *p_h, *p_o, *p_Weff, *p_cvec;
    cudaGetSymbolAddress((void**)&p_h,    g_h);
    cudaGetSymbolAddress((void**)&p_o,    g_o);
    cudaGetSymbolAddress((void**)&p_Weff, g_Weff);
    cudaGetSymbolAddress((void**)&p_cvec, g_cvec);

    const int warpBlocks = (NN * 32 + 255) / 256;

    // ---- CSR build prologue (launch order keeps gemm1 at slot 6 for ncu -s 5) ----
    zero_counts_kernel<<<(NN + 255) / 256, 256>>>();          // 1
    count_kernel<<<1024, 256>>>(e_dst);                       // 2
    scan_block_kernel<<<SCAN_NB, SCAN_B>>>();                 // 3
    scan_sums_kernel<<<1, 128>>>();                           // 4
    add_offsets_kernel<<<SCAN_NB, SCAN_B>>>();                // 5

    // ---- layer 1 GEMM (no CSR dependency; profiled launch #6) ----
    {
        dim3 grid((NN + 127) / 128, TC1 / 128);
        gemm_attn_kernel<128, HEADS><<<grid, 256>>>(x, W1, nullptr, p_h,
                                                    as1, ad1, NN, TC1, IN_C);  // 6
    }
    scatter_kernel<<<1024, 256>>>(e_src, e_dst);              // 7

    agg_kernel<HEADS, HIDC><<<warpBlocks, 256>>>(p_h, b1, p_o);
    zero_stats_kernel<<<1, 256>>>();
    stats_kernel<256><<<512, 256>>>(p_o);
    fold_kernel<<<TC1, 256>>>(W2, gm1, be1, TC1);

    // ---- layer 2 ----
    {
        dim3 grid((NN + 127) / 128, TC1 / 128);
        gemm_attn_kernel<128, HEADS><<<grid, 256>>>(p_o, p_Weff, p_cvec, p_h,
                                                    as2, ad2, NN, TC1, TC1);
    }
    agg_kernel<HEADS, HIDC><<<warpBlocks, 256>>>(p_h, b2, p_o);
    zero_stats_kernel<<<1, 256>>>();
    stats_kernel<256><<<512, 256>>>(p_o);
    fold_kernel<<<HIDC, 256>>>(W3, gm2, be2, HIDC);

    // ---- layer 3 (H=1, C=64) ----
    {
        dim3 grid((NN + 127) / 128, 1);
        gemm_attn_kernel<64, 1><<<grid, 256>>>(p_o, p_Weff, p_cvec, p_h,
                                               as3, ad3, NN, HIDC, TC1);
    }
    agg_kernel<1, HIDC><<<warpBlocks, 256>>>(p_h, b3, p_o);
    zero_stats_kernel<<<1, 256>>>();
    stats_kernel<64><<<512, 256>>>(p_o);

    // ---- pool + BN3-folded classifier ----
    zero_pool_kernel<<<16, 256>>>();
    pool_kernel<<<(NN + POOL_NPB - 1) / POOL_NPB, 256>>>(batch);
    final_kernel<<<NUM_GRAPHS, HIDC>>>(gm3, be3, fcW, fcb, out);
}

// round 7
// speedup vs baseline: 2.5824x; 1.3254x over previous
#include <cuda_runtime.h>
#include <cuda_bf16.h>
#include <cstdint>
#include <math.h>

// Problem constants (fixed by the reference)
#define NN 50000
#define EE 800000
#define IN_C 128
#define HIDC 64
#define HEADS 4
#define TC1 (HEADS * HIDC)   // 256
#define NUM_CLASSES 10
#define NUM_GRAPHS 64
#define EPS 1e-5f
#define NEG_SLOPE 0.2f

#define SCAN_B 512
#define SCAN_NB ((NN + SCAN_B - 1) / SCAN_B)   // 98

// ---------------- device scratch (static globals: no allocation) -------------
__device__ float g_h[(size_t)NN * 256];     // GEMM output / h of current layer
__device__ float g_o[(size_t)NN * 256];     // aggregation output / next input
__device__ float g_as[(size_t)NN * HEADS];
__device__ float g_ad[(size_t)NN * HEADS];
__device__ int   g_rowptr[NN + 1];
__device__ int   g_rowcur[NN];
__device__ int   g_counts[NN];
__device__ int   g_bsums[SCAN_NB + 8];
__device__ int   g_srcs[EE];
__device__ float g_sum[256];
__device__ float g_sumsq[256];
__device__ float g_Wt[256 * 256];           // transposed (BN-folded) weights [N][K]
__device__ float g_cvec[256];
__device__ float g_gsum[NUM_GRAPHS * HIDC];
__device__ int   g_gcnt[NUM_GRAPHS];

// ============================ PTX helpers =====================================
__device__ __forceinline__ uint32_t smem_u32(const void* p) {
    uint32_t a;
    asm("{ .reg .u64 t; cvta.to.shared.u64 t, %1; cvt.u32.u64 %0, t; }"
        : "=r"(a) : "l"(p));
    return a;
}

#define LDSM_X4(r0, r1, r2, r3, addr) \
    asm volatile("ldmatrix.sync.aligned.m8n8.x4.shared.b16 {%0,%1,%2,%3}, [%4];" \
        : "=r"(r0), "=r"(r1), "=r"(r2), "=r"(r3) : "r"(addr))

#define MMA_BF16(d, a, b) \
    asm volatile("mma.sync.aligned.m16n8k16.row.col.f32.bf16.bf16.f32 " \
        "{%0,%1,%2,%3}, {%4,%5,%6,%7}, {%8,%9}, {%0,%1,%2,%3};" \
        : "+f"((d)[0]), "+f"((d)[1]), "+f"((d)[2]), "+f"((d)[3]) \
        : "r"((a)[0]), "r"((a)[1]), "r"((a)[2]), "r"((a)[3]), \
          "r"((b)[0]), "r"((b)[1]))

__device__ __forceinline__ uint32_t pack_bf2(float a, float b) {
    __nv_bfloat162 t = __floats2bfloat162_rn(a, b);
    return *reinterpret_cast<uint32_t*>(&t);
}
// split v into bf16 hi + bf16(residual); store 4 cols (8B) each
__device__ __forceinline__ void split_store4(float4 v, char* hi, char* lo, uint32_t off) {
    float hx = __bfloat162float(__float2bfloat16_rn(v.x));
    float hy = __bfloat162float(__float2bfloat16_rn(v.y));
    float hz = __bfloat162float(__float2bfloat16_rn(v.z));
    float hw = __bfloat162float(__float2bfloat16_rn(v.w));
    uint2 h, l;
    h.x = pack_bf2(hx, hy);            h.y = pack_bf2(hz, hw);
    l.x = pack_bf2(v.x - hx, v.y - hy); l.y = pack_bf2(v.z - hz, v.w - hw);
    *reinterpret_cast<uint2*>(hi + off) = h;
    *reinterpret_cast<uint2*>(lo + off) = l;
}

// ============== bf16-split mma.sync GEMM + fused attention epilogue ===========
// C[M,N_TOT] = A[M,K] @ Bt[N_TOT,K]^T (+cvec); writes g_as/g_ad (H heads).
// CTA tile 128x64 (blockIdx.y = 64-col group = one head). 8 warps, 4(m)x2(n).
// Warp tile 32x32 via m16n8k16; 2-term bf16 split: AhBh + AhBl + AlBh.
#define APITCH 80   // bytes per 32-col bf16 row (64B data + 16B skew)
template<int N_TOT, int H>
__global__ void __launch_bounds__(256, 2)
mma_gemm_kernel(const float* __restrict__ A, const float* __restrict__ Bt,
                const float* __restrict__ cvec, float* __restrict__ C,
                const float* __restrict__ a_srcP, const float* __restrict__ a_dstP,
                int M, int K)
{
    __shared__ __align__(16) char sAh[128 * APITCH];
    __shared__ __align__(16) char sAl[128 * APITCH];
    __shared__ __align__(16) char sBh[64 * APITCH];
    __shared__ __align__(16) char sBl[64 * APITCH];
    __shared__ float sAS[128];
    __shared__ float sAD[128];

    const int tid = threadIdx.x;
    const int lane = tid & 31;
    const int wid = tid >> 5;
    const int warp_m = wid >> 1;        // 0..3
    const int warp_n = wid & 1;         // 0..1
    const int row0 = blockIdx.x * 128;
    const int head = (H == 4) ? blockIdx.y : 0;
    const int colg0 = blockIdx.y * 64;

    if (tid < 128) { sAS[tid] = 0.f; sAD[tid] = 0.f; }

    const uint32_t bAh = smem_u32(sAh), bAl = smem_u32(sAl);
    const uint32_t bBh = smem_u32(sBh), bBl = smem_u32(sBl);

    // per-lane ldmatrix address components
    const uint32_t aRow = (uint32_t)(lane & 15) * APITCH;      // A: rows 0-15
    const uint32_t aSel = (uint32_t)((lane >> 4) & 1) * 16;    // A: k halves
    const uint32_t bRow = (uint32_t)((lane & 7) + ((lane >> 4) & 1) * 8) * APITCH;
    const uint32_t bSel = (uint32_t)((lane >> 3) & 1) * 16;

    float acc[2][4][4];
#pragma unroll
    for (int mf = 0; mf < 2; mf++)
#pragma unroll
        for (int nf = 0; nf < 4; nf++)
#pragma unroll
            for (int q = 0; q < 4; q++) acc[mf][nf][q] = 0.f;

    const int nch = K >> 5;
    for (int ch = 0; ch < nch; ch++) {
        const int k0 = ch << 5;
        // --- convert A tile: 128 x 32 fp32 -> bf16 hi/lo ---
#pragma unroll
        for (int i = 0; i < 4; i++) {
            int idx = tid + (i << 8);
            int r = idx >> 3, c4 = idx & 7;
            int gr = row0 + r;
            float4 v = make_float4(0.f, 0.f, 0.f, 0.f);
            if (gr < M) v = *reinterpret_cast<const float4*>(A + (size_t)gr * K + k0 + (c4 << 2));
            split_store4(v, sAh, sAl, (uint32_t)(r * APITCH + (c4 << 3)));
        }
        // --- convert B tile: 64 x 32 ---
#pragma unroll
        for (int i = 0; i < 2; i++) {
            int idx = tid + (i << 8);
            int r = idx >> 3, c4 = idx & 7;
            float4 v = *reinterpret_cast<const float4*>(
                Bt + (size_t)(colg0 + r) * K + k0 + (c4 << 2));
            split_store4(v, sBh, sBl, (uint32_t)(r * APITCH + (c4 << 3)));
        }
        __syncthreads();

#pragma unroll
        for (int kk = 0; kk < 2; kk++) {
            const uint32_t kOff = (uint32_t)kk * 32;
            uint32_t Ah[2][4], Al[2][4], Bh[4][2], Bl[4][2];
#pragma unroll
            for (int mf = 0; mf < 2; mf++) {
                uint32_t o = (uint32_t)(warp_m * 32 + mf * 16) * APITCH + aRow + kOff + aSel;
                LDSM_X4(Ah[mf][0], Ah[mf][1], Ah[mf][2], Ah[mf][3], bAh + o);
                LDSM_X4(Al[mf][0], Al[mf][1], Al[mf][2], Al[mf][3], bAl + o);
            }
#pragma unroll
            for (int np = 0; np < 2; np++) {
                uint32_t o = (uint32_t)(warp_n * 32 + np * 16) * APITCH + bRow + kOff + bSel;
                LDSM_X4(Bh[2 * np][0], Bh[2 * np][1], Bh[2 * np + 1][0], Bh[2 * np + 1][1], bBh + o);
                LDSM_X4(Bl[2 * np][0], Bl[2 * np][1], Bl[2 * np + 1][0], Bl[2 * np + 1][1], bBl + o);
            }
#pragma unroll
            for (int mf = 0; mf < 2; mf++)
#pragma unroll
                for (int nf = 0; nf < 4; nf++) {
                    MMA_BF16(acc[mf][nf], Ah[mf], Bh[nf]);
                    MMA_BF16(acc[mf][nf], Ah[mf], Bl[nf]);
                    MMA_BF16(acc[mf][nf], Al[mf], Bh[nf]);
                }
        }
        __syncthreads();
    }

    // ---- epilogue: cvec add, C store, fused attention logits ----
    const float* asv = a_srcP + head * 64;
    const float* adv = a_dstP + head * 64;
    const int cq = 2 * (lane & 3);

#pragma unroll
    for (int nf = 0; nf < 4; nf++) {
        int cn = warp_n * 32 + nf * 8 + cq;
        float c0 = cvec ? cvec[colg0 + cn] : 0.f;
        float c1 = cvec ? cvec[colg0 + cn + 1] : 0.f;
#pragma unroll
        for (int mf = 0; mf < 2; mf++) {
            acc[mf][nf][0] += c0; acc[mf][nf][1] += c1;
            acc[mf][nf][2] += c0; acc[mf][nf][3] += c1;
        }
    }

#pragma unroll
    for (int mf = 0; mf < 2; mf++)
#pragma unroll
        for (int half = 0; half < 2; half++) {
            int rl = warp_m * 32 + mf * 16 + (lane >> 2) + half * 8;
            int gr = row0 + rl;
            if (gr < M) {
#pragma unroll
                for (int nf = 0; nf < 4; nf++) {
                    int cn = warp_n * 32 + nf * 8 + cq;
                    *reinterpret_cast<float2*>(C + (size_t)gr * N_TOT + colg0 + cn) =
                        make_float2(acc[mf][nf][half * 2], acc[mf][nf][half * 2 + 1]);
                }
            }
            float psa = 0.f, psd = 0.f;
#pragma unroll
            for (int nf = 0; nf < 4; nf++) {
                int cn = warp_n * 32 + nf * 8 + cq;
                float v0 = acc[mf][nf][half * 2], v1 = acc[mf][nf][half * 2 + 1];
                psa += v0 * asv[cn] + v1 * asv[cn + 1];
                psd += v0 * adv[cn] + v1 * adv[cn + 1];
            }
            psa += __shfl_xor_sync(0xffffffffu, psa, 1);
            psd += __shfl_xor_sync(0xffffffffu, psd, 1);
            psa += __shfl_xor_sync(0xffffffffu, psa, 2);
            psd += __shfl_xor_sync(0xffffffffu, psd, 2);
            if ((lane & 3) == 0) {
                atomicAdd(&sAS[rl], psa);
                atomicAdd(&sAD[rl], psd);
            }
        }
    __syncthreads();
    if (tid < 128) {
        int gr = row0 + tid;
        if (gr < M) {
            g_as[(size_t)gr * H + head] = sAS[tid];
            g_ad[(size_t)gr * H + head] = sAD[tid];
        }
    }
}

// ---------------- small init kernels -----------------------------------------
__global__ void zero_counts_kernel() {
    int i = blockIdx.x * blockDim.x + threadIdx.x;
    if (i < NN) g_counts[i] = 0;
}
__global__ void zero_stats_kernel() {
    int i = threadIdx.x;
    g_sum[i] = 0.f; g_sumsq[i] = 0.f;
}
__global__ void zero_pool_kernel() {
    int i = blockIdx.x * blockDim.x + threadIdx.x;
    if (i < NUM_GRAPHS * HIDC) g_gsum[i] = 0.f;
    if (i < NUM_GRAPHS) g_gcnt[i] = 0;
}

// W1 [128][256] -> g_Wt [256][128]
__global__ void transpose_w1_kernel(const float* __restrict__ W) {
    __shared__ float t[32][33];
    int n0 = blockIdx.x * 32, k0 = blockIdx.y * 32;
    int tx = threadIdx.x, ty = threadIdx.y;
    t[ty][tx] = W[(k0 + ty) * 256 + n0 + tx];
    __syncthreads();
    g_Wt[(n0 + ty) * 128 + k0 + tx] = t[tx][ty];
}

// ---------------- CSR build ---------------------------------------------------
__global__ void count_kernel(const int* __restrict__ dst) {
    int i = blockIdx.x * blockDim.x + threadIdx.x;
    for (; i < EE; i += gridDim.x * blockDim.x)
        atomicAdd(&g_counts[dst[i]], 1);
}

__global__ void scan_block_kernel() {
    __shared__ int sm[SCAN_B];
    int tid = threadIdx.x;
    int i = blockIdx.x * SCAN_B + tid;
    int v = (i < NN) ? g_counts[i] : 0;
    sm[tid] = v;
    __syncthreads();
    for (int off = 1; off < SCAN_B; off <<= 1) {
        int t = (tid >= off) ? sm[tid - off] : 0;
        __syncthreads();
        sm[tid] += t;
        __syncthreads();
    }
    if (i < NN) g_rowptr[i + 1] = sm[tid];
    if (tid == SCAN_B - 1) g_bsums[blockIdx.x] = sm[tid];
}

__global__ void scan_sums_kernel() {
    __shared__ int sm[128];
    int t = threadIdx.x;
    int v = (t < SCAN_NB) ? g_bsums[t] : 0;
    sm[t] = v;
    __syncthreads();
    for (int off = 1; off < 128; off <<= 1) {
        int u = (t >= off) ? sm[t - off] : 0;
        __syncthreads();
        sm[t] += u;
        __syncthreads();
    }
    if (t < SCAN_NB) g_bsums[t] = sm[t] - v;
    if (t == 0) g_rowptr[0] = 0;
}

__global__ void add_offsets_kernel() {
    int i = blockIdx.x * SCAN_B + threadIdx.x;
    if (i < NN) {
        int r = g_rowptr[i + 1] + g_bsums[blockIdx.x];
        g_rowptr[i + 1] = r;
        if (i + 1 < NN) g_rowcur[i + 1] = r;
        if (i == 0) g_rowcur[0] = 0;
    }
}

__global__ void scatter_kernel(const int* __restrict__ src, const int* __restrict__ dst) {
    int i = blockIdx.x * blockDim.x + threadIdx.x;
    for (; i < EE; i += gridDim.x * blockDim.x) {
        int d = dst[i];
        int pos = atomicAdd(&g_rowcur[d], 1);
        g_srcs[pos] = src[i];
    }
}

// ---------------- aggregation: warp per dst node, single-pass softmax ---------
template <int H, int C>
__global__ void __launch_bounds__(256)
agg_kernel(const float* __restrict__ hbuf, const float* __restrict__ bias,
           float* __restrict__ outbuf)
{
    const int TC = H * C;
    const int CPL = TC / 32;
    int wid = (blockIdx.x * blockDim.x + threadIdx.x) >> 5;
    int lane = threadIdx.x & 31;
    if (wid >= NN) return;
    int cb = lane * CPL;
    int hd = cb / C;
    int r0 = g_rowptr[wid];
    int r1 = g_rowptr[wid + 1];
    float adv = g_ad[(size_t)wid * H + hd];

    float den = 0.f;
    float acc[CPL];
#pragma unroll
    for (int i = 0; i < CPL; i++) acc[i] = 0.f;

    for (int e = r0; e < r1; e++) {
        int s = g_srcs[e];
        float ev = g_as[(size_t)s * H + hd] + adv;
        ev = (ev > 0.f) ? ev : NEG_SLOPE * ev;
        float p = __expf(fminf(ev, 60.f));
        den += p;
        const float* hp = hbuf + (size_t)s * TC + cb;
        if (CPL == 2) {
            float2 vv = *reinterpret_cast<const float2*>(hp);
            acc[0] += p * vv.x;
            acc[1] += p * vv.y;
        } else {
#pragma unroll
            for (int q = 0; q < CPL / 4; q++) {
                float4 vv = reinterpret_cast<const float4*>(hp)[q];
                acc[q * 4 + 0] += p * vv.x;
                acc[q * 4 + 1] += p * vv.y;
                acc[q * 4 + 2] += p * vv.z;
                acc[q * 4 + 3] += p * vv.w;
            }
        }
    }

    float inv = (r1 > r0) ? (1.f / den) : 0.f;
#pragma unroll
    for (int i = 0; i < CPL; i++) {
        float o = acc[i] * inv + bias[cb + i];
        outbuf[(size_t)wid * TC + cb + i] = fmaxf(o, 0.f);
    }
}

// ---------------- per-channel sum / sumsq (for BN fold) -----------------------
template <int C>
__global__ void stats_kernel(const float* __restrict__ buf)
{
    const int RPB = 256 / C;
    int ch = threadIdx.x % C;
    int r = blockIdx.x * RPB + threadIdx.x / C;
    int stride = gridDim.x * RPB;
    float s = 0.f, s2 = 0.f;
    for (; r < NN; r += stride) {
        float v = buf[(size_t)r * C + ch];
        s += v;
        s2 += v * v;
    }
    atomicAdd(&g_sum[ch], s);
    atomicAdd(&g_sumsq[ch], s2);
}

// ---------------- fold BN into next weights (TRANSPOSED output) ---------------
// g_Wt[j][k] = s[k]*W[k][j];  g_cvec[j] = sum_k t[k]*W[k][j]
__global__ void fold_kernel(const float* __restrict__ W,
                            const float* __restrict__ gamma,
                            const float* __restrict__ beta,
                            int cout)
{
    __shared__ float red[256];
    int j = blockIdx.x;
    int k = threadIdx.x;   // cin = 256 always
    const float invN = 1.f / (float)NN;
    float mean = g_sum[k] * invN;
    float var  = g_sumsq[k] * invN - mean * mean;
    float s = gamma[k] * rsqrtf(var + EPS);
    float t = beta[k] - mean * s;
    float w = W[k * cout + j];
    g_Wt[j * 256 + k] = s * w;
    red[k] = t * w;
    __syncthreads();
    for (int off = 128; off > 0; off >>= 1) {
        if (k < off) red[k] += red[k + off];
        __syncthreads();
    }
    if (k == 0) g_cvec[j] = red[0];
}

// ---------------- pooling (sorted batch) + classifier -------------------------
#define POOL_NPB 256
__global__ void pool_kernel(const int* __restrict__ batch)
{
    int n0 = blockIdx.x * POOL_NPB;
    int ch = threadIdx.x & 63;
    int sub = threadIdx.x >> 6;
    float accv = 0.f;
    int cur = -1, cnt = 0;
    int nend = n0 + POOL_NPB; if (nend > NN) nend = NN;
    for (int node = n0 + sub; node < nend; node += 4) {
        int g = batch[node];
        if (g != cur) {
            if (cur >= 0) {
                atomicAdd(&g_gsum[cur * HIDC + ch], accv);
                if (ch == 0) atomicAdd(&g_gcnt[cur], cnt);
            }
            cur = g; accv = 0.f; cnt = 0;
        }
        accv += g_o[(size_t)node * HIDC + ch];
        cnt++;
    }
    if (cur >= 0) {
        atomicAdd(&g_gsum[cur * HIDC + ch], accv);
        if (ch == 0) atomicAdd(&g_gcnt[cur], cnt);
    }
}

__global__ void final_kernel(const float* __restrict__ g3, const float* __restrict__ be3,
                             const float* __restrict__ fcW, const float* __restrict__ fcb,
                             float* __restrict__ out)
{
    __shared__ float z[HIDC];
    int g = blockIdx.x;
    int ch = threadIdx.x;
    const float invN = 1.f / (float)NN;
    float cnt = fmaxf((float)g_gcnt[g], 1.f);
    float pooled = g_gsum[g * HIDC + ch] / cnt;
    float mean = g_sum[ch] * invN;
    float var  = g_sumsq[ch] * invN - mean * mean;
    float s = g3[ch] * rsqrtf(var + EPS);
    float t = be3[ch] - mean * s;
    z[ch] = pooled * s + t;
    __syncthreads();
    if (ch < NUM_CLASSES) {
        float a = fcb[ch];
        for (int c = 0; c < HIDC; c++) a += z[c] * fcW[c * NUM_CLASSES + ch];
        out[g * NUM_CLASSES + ch] = a;
    }
}

// ---------------- driver -------------------------------------------------------
extern "C" void kernel_launch(void* const* d_in, const int* in_sizes, int n_in,
                              void* d_out, int out_size)
{
    const float* x      = (const float*)d_in[0];
    const int*   ei     = (const int*)d_in[1];
    const int*   batch  = (const int*)d_in[2];
    const float* W1     = (const float*)d_in[3];
    const float* as1    = (const float*)d_in[4];
    const float* ad1    = (const float*)d_in[5];
    const float* b1     = (const float*)d_in[6];
    const float* gm1    = (const float*)d_in[7];
    const float* be1    = (const float*)d_in[8];
    const float* W2     = (const float*)d_in[9];
    const float* as2    = (const float*)d_in[10];
    const float* ad2    = (const float*)d_in[11];
    const float* b2     = (const float*)d_in[12];
    const float* gm2    = (const float*)d_in[13];
    const float* be2    = (const float*)d_in[14];
    const float* W3     = (const float*)d_in[15];
    const float* as3    = (const float*)d_in[16];
    const float* ad3    = (const float*)d_in[17];
    const float* b3     = (const float*)d_in[18];
    const float* gm3    = (const float*)d_in[19];
    const float* be3    = (const float*)d_in[20];
    const float* fcW    = (const float*)d_in[21];
    const float* fcb    = (const float*)d_in[22];
    float* out = (float*)d_out;

    const int* e_src = ei;
    const int* e_dst = ei + EE;

    float *p_h, *p_o, *p_Wt, *p_cvec;
    cudaGetSymbolAddress((void**)&p_h,    g_h);
    cudaGetSymbolAddress((void**)&p_o,    g_o);
    cudaGetSymbolAddress((void**)&p_Wt,   g_Wt);
    cudaGetSymbolAddress((void**)&p_cvec, g_cvec);

    const int warpBlocks = (NN * 32 + 255) / 256;
    const int gemmGridX = (NN + 127) / 128;   // 391

    // launch order: slot 4 = layer-1 GEMM (the ncu-profiled launch)
    zero_counts_kernel<<<(NN + 255) / 256, 256>>>();                  // 1
    count_kernel<<<1024, 256>>>(e_dst);                               // 2
    transpose_w1_kernel<<<dim3(8, 4), dim3(32, 32)>>>(W1);            // 3
    mma_gemm_kernel<256, 4><<<dim3(gemmGridX, 4), 256>>>(x, p_Wt, nullptr, p_h,
                                                         as1, ad1, NN, IN_C);  // 4
    scan_block_kernel<<<SCAN_NB, SCAN_B>>>();                         // 5
    scan_sums_kernel<<<1, 128>>>();                                   // 6
    add_offsets_kernel<<<SCAN_NB, SCAN_B>>>();                        // 7
    scatter_kernel<<<1024, 256>>>(e_src, e_dst);                      // 8

    agg_kernel<HEADS, HIDC><<<warpBlocks, 256>>>(p_h, b1, p_o);
    zero_stats_kernel<<<1, 256>>>();
    stats_kernel<256><<<512, 256>>>(p_o);
    fold_kernel<<<TC1, 256>>>(W2, gm1, be1, TC1);

    mma_gemm_kernel<256, 4><<<dim3(gemmGridX, 4), 256>>>(p_o, p_Wt, p_cvec, p_h,
                                                         as2, ad2, NN, TC1);
    agg_kernel<HEADS, HIDC><<<warpBlocks, 256>>>(p_h, b2, p_o);
    zero_stats_kernel<<<1, 256>>>();
    stats_kernel<256><<<512, 256>>>(p_o);
    fold_kernel<<<HIDC, 256>>>(W3, gm2, be2, HIDC);

    mma_gemm_kernel<64, 1><<<dim3(gemmGridX, 1), 256>>>(p_o, p_Wt, p_cvec, p_h,
                                                        as3, ad3, NN, TC1);
    agg_kernel<1, HIDC><<<warpBlocks, 256>>>(p_h, b3, p_o);
    zero_stats_kernel<<<1, 256>>>();
    stats_kernel<64><<<512, 256>>>(p_o);

    zero_pool_kernel<<<16, 256>>>();
    pool_kernel<<<(NN + POOL_NPB - 1) / POOL_NPB, 256>>>(batch);
    final_kernel<<<NUM_GRAPHS, HIDC>>>(gm3, be3, fcW, fcb, out);
}

// round 8
// speedup vs baseline: 3.1211x; 1.2086x over previous
#include <cuda_runtime.h>
#include <cuda_fp16.h>
#include <cstdint>
#include <math.h>

// Problem constants (fixed by the reference)
#define NN 50000
#define EE 800000
#define IN_C 128
#define HIDC 64
#define HEADS 4
#define TC1 (HEADS * HIDC)   // 256
#define NUM_CLASSES 10
#define NUM_GRAPHS 64
#define EPS 1e-5f
#define NEG_SLOPE 0.2f

#define SCAN_B 512
#define SCAN_NB ((NN + SCAN_B - 1) / SCAN_B)   // 98

// ---------------- device scratch (static globals: no allocation) -------------
__device__ __half g_h[(size_t)NN * 256];    // GEMM output (fp16) / h of current layer
__device__ float  g_o[(size_t)NN * 256];    // aggregation output / next GEMM input
__device__ float  g_as[(size_t)NN * HEADS];
__device__ float  g_ad[(size_t)NN * HEADS];
__device__ int    g_rowptr[NN + 1];
__device__ int    g_rowcur[NN];
__device__ int    g_counts[NN];
__device__ int    g_bsums[SCAN_NB + 8];
__device__ int    g_srcs[EE];
__device__ float  g_sum[256];
__device__ float  g_sumsq[256];
__device__ float  g_Wt[256 * 256];          // transposed (BN-folded) weights [N][K]
__device__ float  g_cvec[256];
__device__ float  g_gsum[NUM_GRAPHS * HIDC];
__device__ int    g_gcnt[NUM_GRAPHS];

// ============================ PTX helpers =====================================
__device__ __forceinline__ uint32_t smem_u32(const void* p) {
    uint32_t a;
    asm("{ .reg .u64 t; cvta.to.shared.u64 t, %1; cvt.u32.u64 %0, t; }"
        : "=r"(a) : "l"(p));
    return a;
}

#define LDSM_X4(r0, r1, r2, r3, addr) \
    asm volatile("ldmatrix.sync.aligned.m8n8.x4.shared.b16 {%0,%1,%2,%3}, [%4];" \
        : "=r"(r0), "=r"(r1), "=r"(r2), "=r"(r3) : "r"(addr))

#define MMA_F16(d, a, b) \
    asm volatile("mma.sync.aligned.m16n8k16.row.col.f32.f16.f16.f32 " \
        "{%0,%1,%2,%3}, {%4,%5,%6,%7}, {%8,%9}, {%0,%1,%2,%3};" \
        : "+f"((d)[0]), "+f"((d)[1]), "+f"((d)[2]), "+f"((d)[3]) \
        : "r"((a)[0]), "r"((a)[1]), "r"((a)[2]), "r"((a)[3]), \
          "r"((b)[0]), "r"((b)[1]))

__device__ __forceinline__ uint32_t pack_h2(float a, float b) {
    __half2 t = __floats2half2_rn(a, b);
    return *reinterpret_cast<uint32_t*>(&t);
}
// A: split v into fp16 hi + fp16 residual; store 4 cols (8B) each
__device__ __forceinline__ void split_store4(float4 v, char* hi, char* lo, uint32_t off) {
    float hx = __half2float(__float2half_rn(v.x));
    float hy = __half2float(__float2half_rn(v.y));
    float hz = __half2float(__float2half_rn(v.z));
    float hw = __half2float(__float2half_rn(v.w));
    uint2 h, l;
    h.x = pack_h2(hx, hy);              h.y = pack_h2(hz, hw);
    l.x = pack_h2(v.x - hx, v.y - hy);  l.y = pack_h2(v.z - hz, v.w - hw);
    *reinterpret_cast<uint2*>(hi + off) = h;
    *reinterpret_cast<uint2*>(lo + off) = l;
}
// B: single fp16 round, 4 cols (8B)
__device__ __forceinline__ void conv_store4(float4 v, char* dst, uint32_t off) {
    uint2 h;
    h.x = pack_h2(v.x, v.y); h.y = pack_h2(v.z, v.w);
    *reinterpret_cast<uint2*>(dst + off) = h;
}

// ============== fp16-split mma.sync GEMM + fused attention epilogue ===========
// C[M,N_TOT](fp16) = A[M,K] @ Bt[N_TOT,K]^T (+cvec); writes g_as/g_ad (H heads).
// CTA tile 128x64 (blockIdx.y = 64-col group = one head). 8 warps, 4(m)x2(n).
// Warp tile 32x32 via m16n8k16. 2-term fp16 split: (Ah + Al) @ B.
#define APITCH 80   // bytes per 32-col fp16 row (64B data + 16B skew)
template<int N_TOT, int H>
__global__ void __launch_bounds__(256, 2)
mma_gemm_kernel(const float* __restrict__ A, const float* __restrict__ Bt,
                const float* __restrict__ cvec, __half* __restrict__ C,
                const float* __restrict__ a_srcP, const float* __restrict__ a_dstP,
                int M, int K)
{
    __shared__ __align__(16) char sAh[128 * APITCH];
    __shared__ __align__(16) char sAl[128 * APITCH];
    __shared__ __align__(16) char sB[64 * APITCH];
    __shared__ float sAS[128];
    __shared__ float sAD[128];

    const int tid = threadIdx.x;
    const int lane = tid & 31;
    const int wid = tid >> 5;
    const int warp_m = wid >> 1;        // 0..3
    const int warp_n = wid & 1;         // 0..1
    const int row0 = blockIdx.x * 128;
    const int head = (H == 4) ? blockIdx.y : 0;
    const int colg0 = blockIdx.y * 64;

    if (tid < 128) { sAS[tid] = 0.f; sAD[tid] = 0.f; }

    const uint32_t bAh = smem_u32(sAh), bAl = smem_u32(sAl);
    const uint32_t bB = smem_u32(sB);

    // per-lane ldmatrix address components
    const uint32_t aRow = (uint32_t)(lane & 15) * APITCH;      // A: rows 0-15
    const uint32_t aSel = (uint32_t)((lane >> 4) & 1) * 16;    // A: k halves
    const uint32_t bRow = (uint32_t)((lane & 7) + ((lane >> 4) & 1) * 8) * APITCH;
    const uint32_t bSel = (uint32_t)((lane >> 3) & 1) * 16;

    float acc[2][4][4];
#pragma unroll
    for (int mf = 0; mf < 2; mf++)
#pragma unroll
        for (int nf = 0; nf < 4; nf++)
#pragma unroll
            for (int q = 0; q < 4; q++) acc[mf][nf][q] = 0.f;

    const int nch = K >> 5;
    for (int ch = 0; ch < nch; ch++) {
        const int k0 = ch << 5;
        // --- convert A tile: 128 x 32 fp32 -> fp16 hi/lo ---
#pragma unroll
        for (int i = 0; i < 4; i++) {
            int idx = tid + (i << 8);
            int r = idx >> 3, c4 = idx & 7;
            int gr = row0 + r;
            float4 v = make_float4(0.f, 0.f, 0.f, 0.f);
            if (gr < M) v = *reinterpret_cast<const float4*>(A + (size_t)gr * K + k0 + (c4 << 2));
            split_store4(v, sAh, sAl, (uint32_t)(r * APITCH + (c4 << 3)));
        }
        // --- convert B tile: 64 x 32 (single fp16) ---
        {
            int idx = tid;
            int r = idx >> 3, c4 = idx & 7;
            float4 v = *reinterpret_cast<const float4*>(
                Bt + (size_t)(colg0 + r) * K + k0 + (c4 << 2));
            conv_store4(v, sB, (uint32_t)(r * APITCH + (c4 << 3)));
            idx = tid + 256;
            r = idx >> 3; c4 = idx & 7;
            v = *reinterpret_cast<const float4*>(
                Bt + (size_t)(colg0 + r) * K + k0 + (c4 << 2));
            conv_store4(v, sB, (uint32_t)(r * APITCH + (c4 << 3)));
        }
        __syncthreads();

#pragma unroll
        for (int kk = 0; kk < 2; kk++) {
            const uint32_t kOff = (uint32_t)kk * 32;
            uint32_t Ah[2][4], Al[2][4], Bf[4][2];
#pragma unroll
            for (int mf = 0; mf < 2; mf++) {
                uint32_t o = (uint32_t)(warp_m * 32 + mf * 16) * APITCH + aRow + kOff + aSel;
                LDSM_X4(Ah[mf][0], Ah[mf][1], Ah[mf][2], Ah[mf][3], bAh + o);
                LDSM_X4(Al[mf][0], Al[mf][1], Al[mf][2], Al[mf][3], bAl + o);
            }
#pragma unroll
            for (int np = 0; np < 2; np++) {
                uint32_t o = (uint32_t)(warp_n * 32 + np * 16) * APITCH + bRow + kOff + bSel;
                LDSM_X4(Bf[2 * np][0], Bf[2 * np][1], Bf[2 * np + 1][0], Bf[2 * np + 1][1], bB + o);
            }
#pragma unroll
            for (int mf = 0; mf < 2; mf++)
#pragma unroll
                for (int nf = 0; nf < 4; nf++) {
                    MMA_F16(acc[mf][nf], Ah[mf], Bf[nf]);
                    MMA_F16(acc[mf][nf], Al[mf], Bf[nf]);
                }
        }
        __syncthreads();
    }

    // ---- epilogue: cvec add, C store (fp16), fused attention logits ----
    const float* asv = a_srcP + head * 64;
    const float* adv = a_dstP + head * 64;
    const int cq = 2 * (lane & 3);

#pragma unroll
    for (int nf = 0; nf < 4; nf++) {
        int cn = warp_n * 32 + nf * 8 + cq;
        float c0 = cvec ? cvec[colg0 + cn] : 0.f;
        float c1 = cvec ? cvec[colg0 + cn + 1] : 0.f;
#pragma unroll
        for (int mf = 0; mf < 2; mf++) {
            acc[mf][nf][0] += c0; acc[mf][nf][1] += c1;
            acc[mf][nf][2] += c0; acc[mf][nf][3] += c1;
        }
    }

#pragma unroll
    for (int mf = 0; mf < 2; mf++)
#pragma unroll
        for (int half_ = 0; half_ < 2; half_++) {
            int rl = warp_m * 32 + mf * 16 + (lane >> 2) + half_ * 8;
            int gr = row0 + rl;
            if (gr < M) {
#pragma unroll
                for (int nf = 0; nf < 4; nf++) {
                    int cn = warp_n * 32 + nf * 8 + cq;
                    *reinterpret_cast<__half2*>(C + (size_t)gr * N_TOT + colg0 + cn) =
                        __floats2half2_rn(acc[mf][nf][half_ * 2], acc[mf][nf][half_ * 2 + 1]);
                }
            }
            float psa = 0.f, psd = 0.f;
#pragma unroll
            for (int nf = 0; nf < 4; nf++) {
                int cn = warp_n * 32 + nf * 8 + cq;
                float v0 = acc[mf][nf][half_ * 2], v1 = acc[mf][nf][half_ * 2 + 1];
                psa += v0 * asv[cn] + v1 * asv[cn + 1];
                psd += v0 * adv[cn] + v1 * adv[cn + 1];
            }
            psa += __shfl_xor_sync(0xffffffffu, psa, 1);
            psd += __shfl_xor_sync(0xffffffffu, psd, 1);
            psa += __shfl_xor_sync(0xffffffffu, psa, 2);
            psd += __shfl_xor_sync(0xffffffffu, psd, 2);
            if ((lane & 3) == 0) {
                atomicAdd(&sAS[rl], psa);
                atomicAdd(&sAD[rl], psd);
            }
        }
    __syncthreads();
    if (tid < 128) {
        int gr = row0 + tid;
        if (gr < M) {
            g_as[(size_t)gr * H + head] = sAS[tid];
            g_ad[(size_t)gr * H + head] = sAD[tid];
        }
    }
}

// ---------------- small init kernels -----------------------------------------
__global__ void zero_counts_kernel() {
    int i = blockIdx.x * blockDim.x + threadIdx.x;
    if (i < NN) g_counts[i] = 0;
}
__global__ void zero_stats_kernel() {
    int i = threadIdx.x;
    g_sum[i] = 0.f; g_sumsq[i] = 0.f;
}
__global__ void zero_pool_kernel() {
    int i = blockIdx.x * blockDim.x + threadIdx.x;
    if (i < NUM_GRAPHS * HIDC) g_gsum[i] = 0.f;
    if (i < NUM_GRAPHS) g_gcnt[i] = 0;
}

// W1 [128][256] -> g_Wt [256][128]
__global__ void transpose_w1_kernel(const float* __restrict__ W) {
    __shared__ float t[32][33];
    int n0 = blockIdx.x * 32, k0 = blockIdx.y * 32;
    int tx = threadIdx.x, ty = threadIdx.y;
    t[ty][tx] = W[(k0 + ty) * 256 + n0 + tx];
    __syncthreads();
    g_Wt[(n0 + ty) * 128 + k0 + tx] = t[tx][ty];
}

// ---------------- CSR build ---------------------------------------------------
__global__ void count_kernel(const int* __restrict__ dst) {
    int i = blockIdx.x * blockDim.x + threadIdx.x;
    for (; i < EE; i += gridDim.x * blockDim.x)
        atomicAdd(&g_counts[dst[i]], 1);
}

__global__ void scan_block_kernel() {
    __shared__ int sm[SCAN_B];
    int tid = threadIdx.x;
    int i = blockIdx.x * SCAN_B + tid;
    int v = (i < NN) ? g_counts[i] : 0;
    sm[tid] = v;
    __syncthreads();
    for (int off = 1; off < SCAN_B; off <<= 1) {
        int t = (tid >= off) ? sm[tid - off] : 0;
        __syncthreads();
        sm[tid] += t;
        __syncthreads();
    }
    if (i < NN) g_rowptr[i + 1] = sm[tid];
    if (tid == SCAN_B - 1) g_bsums[blockIdx.x] = sm[tid];
}

__global__ void scan_sums_kernel() {
    __shared__ int sm[128];
    int t = threadIdx.x;
    int v = (t < SCAN_NB) ? g_bsums[t] : 0;
    sm[t] = v;
    __syncthreads();
    for (int off = 1; off < 128; off <<= 1) {
        int u = (t >= off) ? sm[t - off] : 0;
        __syncthreads();
        sm[t] += u;
        __syncthreads();
    }
    if (t < SCAN_NB) g_bsums[t] = sm[t] - v;
    if (t == 0) g_rowptr[0] = 0;
}

__global__ void add_offsets_kernel() {
    int i = blockIdx.x * SCAN_B + threadIdx.x;
    if (i < NN) {
        int r = g_rowptr[i + 1] + g_bsums[blockIdx.x];
        g_rowptr[i + 1] = r;
        if (i + 1 < NN) g_rowcur[i + 1] = r;
        if (i == 0) g_rowcur[0] = 0;
    }
}

__global__ void scatter_kernel(const int* __restrict__ src, const int* __restrict__ dst) {
    int i = blockIdx.x * blockDim.x + threadIdx.x;
    for (; i < EE; i += gridDim.x * blockDim.x) {
        int d = dst[i];
        int pos = atomicAdd(&g_rowcur[d], 1);
        g_srcs[pos] = src[i];
    }
}

// ---------------- aggregation: warp per dst node, single-pass softmax ---------
// h read as fp16 (half traffic); math in fp32.
template <int H, int C>
__global__ void __launch_bounds__(256)
agg_kernel(const __half* __restrict__ hbuf, const float* __restrict__ bias,
           float* __restrict__ outbuf)
{
    const int TC = H * C;
    const int CPL = TC / 32;    // 8 (H=4) or 2 (H=1)
    int wid = (blockIdx.x * blockDim.x + threadIdx.x) >> 5;
    int lane = threadIdx.x & 31;
    if (wid >= NN) return;
    int cb = lane * CPL;
    int hd = cb / C;
    int r0 = g_rowptr[wid];
    int r1 = g_rowptr[wid + 1];
    float adv = g_ad[(size_t)wid * H + hd];

    float den = 0.f;
    float acc[CPL];
#pragma unroll
    for (int i = 0; i < CPL; i++) acc[i] = 0.f;

    for (int e = r0; e < r1; e++) {
        int s = g_srcs[e];
        float ev = g_as[(size_t)s * H + hd] + adv;
        ev = (ev > 0.f) ? ev : NEG_SLOPE * ev;
        float p = __expf(fminf(ev, 60.f));
        den += p;
        const __half* hp = hbuf + (size_t)s * TC + cb;
        if (CPL == 2) {
            float2 f = __half22float2(*reinterpret_cast<const __half2*>(hp));
            acc[0] += p * f.x;
            acc[1] += p * f.y;
        } else {
            uint4 u = *reinterpret_cast<const uint4*>(hp);   // 8 halfs, one 16B load
            const __half2* hh = reinterpret_cast<const __half2*>(&u);
#pragma unroll
            for (int q = 0; q < 4; q++) {
                float2 f = __half22float2(hh[q]);
                acc[q * 2 + 0] += p * f.x;
                acc[q * 2 + 1] += p * f.y;
            }
        }
    }

    float inv = (r1 > r0) ? (1.f / den) : 0.f;
#pragma unroll
    for (int i = 0; i < CPL; i++) {
        float o = acc[i] * inv + bias[cb + i];
        outbuf[(size_t)wid * TC + cb + i] = fmaxf(o, 0.f);
    }
}

// ---------------- per-channel sum / sumsq (for BN fold) -----------------------
template <int C>
__global__ void stats_kernel(const float* __restrict__ buf)
{
    const int RPB = 256 / C;
    int ch = threadIdx.x % C;
    int r = blockIdx.x * RPB + threadIdx.x / C;
    int stride = gridDim.x * RPB;
    float s = 0.f, s2 = 0.f;
    for (; r < NN; r += stride) {
        float v = buf[(size_t)r * C + ch];
        s += v;
        s2 += v * v;
    }
    atomicAdd(&g_sum[ch], s);
    atomicAdd(&g_sumsq[ch], s2);
}

// ---------------- fold BN into next weights (TRANSPOSED output) ---------------
// g_Wt[j][k] = s[k]*W[k][j];  g_cvec[j] = sum_k t[k]*W[k][j]
__global__ void fold_kernel(const float* __restrict__ W,
                            const float* __restrict__ gamma,
                            const float* __restrict__ beta,
                            int cout)
{
    __shared__ float red[256];
    int j = blockIdx.x;
    int k = threadIdx.x;   // cin = 256 always
    const float invN = 1.f / (float)NN;
    float mean = g_sum[k] * invN;
    float var  = g_sumsq[k] * invN - mean * mean;
    float s = gamma[k] * rsqrtf(var + EPS);
    float t = beta[k] - mean * s;
    float w = W[k * cout + j];
    g_Wt[j * 256 + k] = s * w;
    red[k] = t * w;
    __syncthreads();
    for (int off = 128; off > 0; off >>= 1) {
        if (k < off) red[k] += red[k + off];
        __syncthreads();
    }
    if (k == 0) g_cvec[j] = red[0];
}

// ---------------- pooling (sorted batch) + classifier -------------------------
#define POOL_NPB 256
__global__ void pool_kernel(const int* __restrict__ batch)
{
    int n0 = blockIdx.x * POOL_NPB;
    int ch = threadIdx.x & 63;
    int sub = threadIdx.x >> 6;
    float accv = 0.f;
    int cur = -1, cnt = 0;
    int nend = n0 + POOL_NPB; if (nend > NN) nend = NN;
    for (int node = n0 + sub; node < nend; node += 4) {
        int g = batch[node];
        if (g != cur) {
            if (cur >= 0) {
                atomicAdd(&g_gsum[cur * HIDC + ch], accv);
                if (ch == 0) atomicAdd(&g_gcnt[cur], cnt);
            }
            cur = g; accv = 0.f; cnt = 0;
        }
        accv += g_o[(size_t)node * HIDC + ch];
        cnt++;
    }
    if (cur >= 0) {
        atomicAdd(&g_gsum[cur * HIDC + ch], accv);
        if (ch == 0) atomicAdd(&g_gcnt[cur], cnt);
    }
}

__global__ void final_kernel(const float* __restrict__ g3, const float* __restrict__ be3,
                             const float* __restrict__ fcW, const float* __restrict__ fcb,
                             float* __restrict__ out)
{
    __shared__ float z[HIDC];
    int g = blockIdx.x;
    int ch = threadIdx.x;
    const float invN = 1.f / (float)NN;
    float cnt = fmaxf((float)g_gcnt[g], 1.f);
    float pooled = g_gsum[g * HIDC + ch] / cnt;
    float mean = g_sum[ch] * invN;
    float var  = g_sumsq[ch] * invN - mean * mean;
    float s = g3[ch] * rsqrtf(var + EPS);
    float t = be3[ch] - mean * s;
    z[ch] = pooled * s + t;
    __syncthreads();
    if (ch < NUM_CLASSES) {
        float a = fcb[ch];
        for (int c = 0; c < HIDC; c++) a += z[c] * fcW[c * NUM_CLASSES + ch];
        out[g * NUM_CLASSES + ch] = a;
    }
}

// ---------------- driver -------------------------------------------------------
extern "C" void kernel_launch(void* const* d_in, const int* in_sizes, int n_in,
                              void* d_out, int out_size)
{
    const float* x      = (const float*)d_in[0];
    const int*   ei     = (const int*)d_in[1];
    const int*   batch  = (const int*)d_in[2];
    const float* W1     = (const float*)d_in[3];
    const float* as1    = (const float*)d_in[4];
    const float* ad1    = (const float*)d_in[5];
    const float* b1     = (const float*)d_in[6];
    const float* gm1    = (const float*)d_in[7];
    const float* be1    = (const float*)d_in[8];
    const float* W2     = (const float*)d_in[9];
    const float* as2    = (const float*)d_in[10];
    const float* ad2    = (const float*)d_in[11];
    const float* b2     = (const float*)d_in[12];
    const float* gm2    = (const float*)d_in[13];
    const float* be2    = (const float*)d_in[14];
    const float* W3     = (const float*)d_in[15];
    const float* as3    = (const float*)d_in[16];
    const float* ad3    = (const float*)d_in[17];
    const float* b3     = (const float*)d_in[18];
    const float* gm3    = (const float*)d_in[19];
    const float* be3    = (const float*)d_in[20];
    const float* fcW    = (const float*)d_in[21];
    const float* fcb    = (const float*)d_in[22];
    float* out = (float*)d_out;

    const int* e_src = ei;
    const int* e_dst = ei + EE;

    __half* p_h;
    float *p_o, *p_Wt, *p_cvec;
    cudaGetSymbolAddress((void**)&p_h,    g_h);
    cudaGetSymbolAddress((void**)&p_o,    g_o);
    cudaGetSymbolAddress((void**)&p_Wt,   g_Wt);
    cudaGetSymbolAddress((void**)&p_cvec, g_cvec);

    const int warpBlocks = (NN * 32 + 255) / 256;
    const int gemmGridX = (NN + 127) / 128;   // 391

    // launch order: slot 4 = layer-1 GEMM (the ncu-profiled launch)
    zero_counts_kernel<<<(NN + 255) / 256, 256>>>();                  // 1
    count_kernel<<<1024, 256>>>(e_dst);                               // 2
    transpose_w1_kernel<<<dim3(8, 4), dim3(32, 32)>>>(W1);            // 3
    mma_gemm_kernel<256, 4><<<dim3(gemmGridX, 4), 256>>>(x, p_Wt, nullptr, p_h,
                                                         as1, ad1, NN, IN_C);  // 4
    scan_block_kernel<<<SCAN_NB, SCAN_B>>>();                         // 5
    scan_sums_kernel<<<1, 128>>>();                                   // 6
    add_offsets_kernel<<<SCAN_NB, SCAN_B>>>();                        // 7
    scatter_kernel<<<1024, 256>>>(e_src, e_dst);                      // 8

    agg_kernel<HEADS, HIDC><<<warpBlocks, 256>>>(p_h, b1, p_o);
    zero_stats_kernel<<<1, 256>>>();
    stats_kernel<256><<<512, 256>>>(p_o);
    fold_kernel<<<TC1, 256>>>(W2, gm1, be1, TC1);

    mma_gemm_kernel<256, 4><<<dim3(gemmGridX, 4), 256>>>(p_o, p_Wt, p_cvec, p_h,
                                                         as2, ad2, NN, TC1);
    agg_kernel<HEADS, HIDC><<<warpBlocks, 256>>>(p_h, b2, p_o);
    zero_stats_kernel<<<1, 256>>>();
    stats_kernel<256><<<512, 256>>>(p_o);
    fold_kernel<<<HIDC, 256>>>(W3, gm2, be2, HIDC);

    mma_gemm_kernel<64, 1><<<dim3(gemmGridX, 1), 256>>>(p_o, p_Wt, p_cvec, p_h,
                                                        as3, ad3, NN, TC1);
    agg_kernel<1, HIDC><<<warpBlocks, 256>>>(p_h, b3, p_o);
    zero_stats_kernel<<<1, 256>>>();
    stats_kernel<64><<<512, 256>>>(p_o);

    zero_pool_kernel<<<16, 256>>>();
    pool_kernel<<<(NN + POOL_NPB - 1) / POOL_NPB, 256>>>(batch);
    final_kernel<<<NUM_GRAPHS, HIDC>>>(gm3, be3, fcW, fcb, out);
}